// round 5
// baseline (speedup 1.0000x reference)
#include <cuda_runtime.h>
#include <cstdint>

#define HD  256
#define NB  128
#define PPN 1024
#define LGN 128

// ---------------- device scratch (no allocation allowed) ----------------
// bf16x2-packed tables: [row][128] uint32, word = (col j even in low, j+1 in high)
__device__ __align__(16) unsigned g_EW_elem[128 * 128];
__device__ __align__(16) unsigned g_EW_abb[64 * 128];    // (E_aa + E_bb)@Wd1 + bd1
__device__ __align__(16) unsigned g_EW_lig[16 * 128];    // E_lig@Wd1 + bd1
// fused affinity matrix: rows 0-255 = Wd2@Wa1_p, 256-511 = Wd2@Wa1_l,
// 512-513 = Wa1 contact rows, 514 = c0 = bd2@(Wa1_p+Wa1_l)+ba1
__device__ __align__(16) float g_M[515 * HD];
__device__ __align__(16) float g_pooled[256 * HD];       // rows 0..127 protein, 128..255 ligand
__device__ __align__(8)  float g_contact[NB * 2];

// ---------------- packed f32x2 helpers ----------------
__device__ __forceinline__ uint64_t pk2(float a, float b) {
    uint64_t r; asm("mov.b64 %0,{%1,%2};" : "=l"(r) : "f"(a), "f"(b)); return r;
}
__device__ __forceinline__ uint64_t pkf2(float2 v) { return pk2(v.x, v.y); }
__device__ __forceinline__ float2 upk(uint64_t v) {
    float2 r; asm("mov.b64 {%0,%1},%2;" : "=f"(r.x), "=f"(r.y) : "l"(v)); return r;
}
__device__ __forceinline__ uint64_t f2fma(uint64_t a, uint64_t b, uint64_t c) {
    uint64_t d; asm("fma.rn.f32x2 %0,%1,%2,%3;" : "=l"(d) : "l"(a), "l"(b), "l"(c)); return d;
}
__device__ __forceinline__ uint64_t f2add(uint64_t a, uint64_t b) {
    uint64_t d; asm("add.rn.f32x2 %0,%1,%2;" : "=l"(d) : "l"(a), "l"(b)); return d;
}
__device__ __forceinline__ uint64_t f2mul(uint64_t a, uint64_t b) {
    uint64_t d; asm("mul.rn.f32x2 %0,%1,%2;" : "=l"(d) : "l"(a), "l"(b)); return d;
}
__device__ __forceinline__ unsigned cvt_bf16x2(float hi, float lo) {
    unsigned u; asm("cvt.rn.bf16x2.f32 %0,%1,%2;" : "=r"(u) : "f"(hi), "f"(lo)); return u;
}
__device__ __forceinline__ unsigned bf2add(unsigned a, unsigned b) {
    unsigned r; asm("add.rn.bf16x2 %0,%1,%2;" : "=r"(r) : "r"(a), "r"(b)); return r;
}
__device__ __forceinline__ uint64_t bf2_to_f2(unsigned u) {
    return pk2(__uint_as_float(u << 16), __uint_as_float(u & 0xffff0000u));
}

// =====================================================================
// K_pre v2: grid 91 x 256. 8 output rows/block, LDG.128 weight stream.
//   blk 0..25 : EW rows (8/block, 208 rows)
//   blk 26..89: M rows (8/block, 512 rows)
//   blk 90    : c0 row + contact-weight row copies
// Thread (ks = tid>>6, jt = tid&63): k-slice of 64, 4 cols j0=jt*4.
// Row-pair packed accumulators: acc[rp][c] = (row 2rp, row 2rp+1) at col c.
// =====================================================================
__global__ __launch_bounds__(256) void k_pre(
    const float* __restrict__ E_elem, const float* __restrict__ E_aa,
    const float* __restrict__ E_bb,   const float* __restrict__ E_lig,
    const float* __restrict__ Wd1,    const float* __restrict__ bd1,
    const float* __restrict__ Wd2,    const float* __restrict__ bd2,
    const float* __restrict__ Wa1,    const float* __restrict__ ba1)
{
    __shared__ __align__(16) float sE[256 * 8];            // [k][r], r=0..7
    __shared__ __align__(16) uint64_t s_part[4 * 64 * 16]; // [ks][jt][rp*4+c]
    const int blk = blockIdx.x;
    const int tid = threadIdx.x;

    if (blk == 90) {
        // ------- c0 row + contact weight rows -------
        sE[tid] = bd2[tid];
        __syncthreads();
        const int j = tid;
        float acc = 0.0f;
        #pragma unroll 8
        for (int m = 0; m < 256; m++)
            acc = fmaf(sE[m], Wa1[m * HD + j] + Wa1[(256 + m) * HD + j], acc);
        g_M[514 * HD + j] = acc + ba1[j];
        g_M[512 * HD + j] = Wa1[512 * HD + j];
        g_M[513 * HD + j] = Wa1[513 * HD + j];
        return;
    }

    const bool is_ew = (blk < 26);
    const int r0  = is_ew ? blk * 8 : 0;
    const int mr0 = is_ew ? 0 : (blk - 26) * 8;
    const float* W;   // weight matrix whose rows are indexed by k
    if (is_ew) W = Wd1;
    else       W = Wa1 + ((mr0 >= 256) ? 256 * HD : 0);

    // ---- stage sE[k][r]: 8 source rows, transposed ----
    {
        const int k = tid;
        float v[8];
        if (is_ew) {
            #pragma unroll
            for (int r = 0; r < 8; r++) {
                int gr = r0 + r;
                if (gr < 128) v[r] = E_elem[gr * HD + k];
                else if (gr < 192) {
                    int idx = gr - 128;
                    v[r] = E_aa[(idx >> 1) * HD + k] + E_bb[(idx & 1) * HD + k];
                } else v[r] = E_lig[(gr - 192) * HD + k];
            }
        } else {
            const int k0 = mr0 & 255;
            #pragma unroll
            for (int r = 0; r < 8; r++) v[r] = Wd2[(k0 + r) * HD + k];
        }
        float4* s4 = (float4*)(sE + k * 8);
        s4[0] = make_float4(v[0], v[1], v[2], v[3]);
        s4[1] = make_float4(v[4], v[5], v[6], v[7]);
    }
    __syncthreads();

    const int jt = tid & 63, ks = tid >> 6;
    const float4* W4 = (const float4*)W;   // [k*64 + jt]

    uint64_t acc[4][4];
    #pragma unroll
    for (int rp = 0; rp < 4; rp++)
        #pragma unroll
        for (int c = 0; c < 4; c++) acc[rp][c] = 0ull;

    const int kbase = ks * 64;
    #pragma unroll 8
    for (int kk = 0; kk < 64; kk++) {
        const int k = kbase + kk;
        float4 w = W4[k * 64 + jt];
        uint64_t wd[4] = {pk2(w.x, w.x), pk2(w.y, w.y), pk2(w.z, w.z), pk2(w.w, w.w)};
        const ulonglong2* e2 = (const ulonglong2*)(sE + k * 8);
        ulonglong2 eA = e2[0];   // row-pairs (0,1) and (2,3)
        ulonglong2 eB = e2[1];   // row-pairs (4,5) and (6,7)
        uint64_t ep[4] = {eA.x, eA.y, eB.x, eB.y};
        #pragma unroll
        for (int rp = 0; rp < 4; rp++)
            #pragma unroll
            for (int c = 0; c < 4; c++)
                acc[rp][c] = f2fma(ep[rp], wd[c], acc[rp][c]);
    }

    // ---- write partials ----
    {
        uint64_t* dst = s_part + ((ks * 64 + jt) * 16);
        #pragma unroll
        for (int rp = 0; rp < 4; rp++)
            #pragma unroll
            for (int c = 0; c < 4; c++) dst[rp * 4 + c] = acc[rp][c];
    }
    __syncthreads();

    // ---- reduce over 4 k-slices; thread (jt2, rp2) handles row-pair rp2, 4 cols ----
    {
        const int jt2 = tid & 63, rp2 = tid >> 6;
        uint64_t s[4];
        #pragma unroll
        for (int c = 0; c < 4; c++) s[c] = 0ull;
        #pragma unroll
        for (int sl = 0; sl < 4; sl++) {
            const uint64_t* src = s_part + ((sl * 64 + jt2) * 16) + rp2 * 4;
            #pragma unroll
            for (int c = 0; c < 4; c++) s[c] = f2add(s[c], src[c]);
        }
        const int j0 = jt2 * 4;
        float lo[4], hi[4];   // lo = row 2rp2, hi = row 2rp2+1
        #pragma unroll
        for (int c = 0; c < 4; c++) { float2 v = upk(s[c]); lo[c] = v.x; hi[c] = v.y; }

        if (is_ew) {
            const int gr_lo = r0 + 2 * rp2, gr_hi = gr_lo + 1;
            if (gr_lo >= 128) {
                #pragma unroll
                for (int c = 0; c < 4; c++) {
                    float b = bd1[j0 + c];
                    lo[c] += b; hi[c] += b;
                }
            }
            unsigned wlo0 = cvt_bf16x2(lo[1], lo[0]), wlo1 = cvt_bf16x2(lo[3], lo[2]);
            unsigned whi0 = cvt_bf16x2(hi[1], hi[0]), whi1 = cvt_bf16x2(hi[3], hi[2]);
            const int col = jt2 * 2;   // word index within 128-word row
            unsigned *rl, *rh;
            if (gr_lo < 128)      { rl = g_EW_elem + gr_lo * 128; rh = g_EW_elem + gr_hi * 128; }
            else if (gr_lo < 192) { rl = g_EW_abb + (gr_lo - 128) * 128; rh = g_EW_abb + (gr_hi - 128) * 128; }
            else                  { rl = g_EW_lig + (gr_lo - 192) * 128; rh = g_EW_lig + (gr_hi - 192) * 128; }
            ((uint2*)(rl + col))[0] = make_uint2(wlo0, wlo1);
            ((uint2*)(rh + col))[0] = make_uint2(whi0, whi1);
        } else {
            const int mr_lo = mr0 + 2 * rp2, mr_hi = mr_lo + 1;
            ((float4*)(g_M + mr_lo * HD + j0))[0] = make_float4(lo[0], lo[1], lo[2], lo[3]);
            ((float4*)(g_M + mr_hi * HD + j0))[0] = make_float4(hi[0], hi[1], hi[2], hi[3]);
        }
    }
}

// =====================================================================
// K_bc: grid 384 x 256, dynamic smem 110592B.
//   blk 0..127   : protein pool (bf16 tables in smem, quadratic silu)
//   blk 128..255 : ligand pool
//   blk 256..383 : contact features
// =====================================================================
__global__ __launch_bounds__(256, 1) void k_bc(
    const float* __restrict__ ppos, const float* __restrict__ lpos,
    const int* __restrict__ p_elem, const int* __restrict__ p_aa,
    const int* __restrict__ p_bb,   const int* __restrict__ l_type)
{
    extern __shared__ float smf[];
    const int blk = blockIdx.x;
    const int tid = threadIdx.x;

    if (blk < 128) {
        const int b = blk;
        unsigned* s_tab = (unsigned*)smf;
        int2*     s_off = (int2*)(s_tab + 16384 + 8192);
        float4*   s_red = (float4*)(s_off + 1024);

        {
            uint4* dst = (uint4*)s_tab;
            const uint4* src = (const uint4*)g_EW_elem;
            for (int i = tid; i < 4096; i += 256) dst[i] = src[i];
            dst = (uint4*)(s_tab + 16384);
            src = (const uint4*)g_EW_abb;
            for (int i = tid; i < 2048; i += 256) dst[i] = src[i];
        }
        const int base = b * PPN;
        for (int n = tid; n < PPN; n += 256) {
            int e = p_elem[base + n], a = p_aa[base + n], bb = p_bb[base + n];
            s_off[n] = make_int2(e * 128, 16384 + (a * 2 + bb) * 128);
        }
        __syncthreads();

        const int half = tid >> 7, tc = tid & 127;
        uint64_t accL = 0ull, accQ = 0ull;
        const int n0 = half * 512;
        #pragma unroll 8
        for (int n = n0; n < n0 + 512; n++) {
            int2 off = s_off[n];
            unsigned ue = s_tab[off.x + tc];
            unsigned ua = s_tab[off.y + tc];
            uint64_t x = bf2_to_f2(bf2add(ue, ua));
            accL = f2add(accL, x);
            accQ = f2fma(x, x, accQ);
        }
        float2 l = upk(accL), q = upk(accQ);
        s_red[tid] = make_float4(l.x, l.y, q.x, q.y);
        __syncthreads();
        if (tid < 128) {
            float4 a0 = s_red[tid], a1 = s_red[128 + tid];
            float2 r;
            r.x = (a0.x + a1.x) * (0.5f / 1024.0f) + (a0.z + a1.z) * (0.25f / 1024.0f);
            r.y = (a0.y + a1.y) * (0.5f / 1024.0f) + (a0.w + a1.w) * (0.25f / 1024.0f);
            ((float2*)g_pooled)[b * 128 + tid] = r;
        }
    } else if (blk < 256) {
        const int b = blk - 128;
        unsigned* s_tab = (unsigned*)smf;
        int*      s_t   = (int*)(s_tab + 2048);
        float4*   s_red = (float4*)(s_t + 128);

        {
            uint4* dst = (uint4*)s_tab;
            const uint4* src = (const uint4*)g_EW_lig;
            for (int i = tid; i < 512; i += 256) dst[i] = src[i];
        }
        const int base = b * LGN;
        if (tid < 128) s_t[tid] = l_type[base + tid] * 128;
        __syncthreads();

        const int half = tid >> 7, tc = tid & 127;
        uint64_t accL = 0ull, accQ = 0ull;
        const int n0 = half * 64;
        #pragma unroll 8
        for (int n = n0; n < n0 + 64; n++) {
            uint64_t x = bf2_to_f2(s_tab[s_t[n] + tc]);
            accL = f2add(accL, x);
            accQ = f2fma(x, x, accQ);
        }
        float2 l = upk(accL), q = upk(accQ);
        s_red[tid] = make_float4(l.x, l.y, q.x, q.y);
        __syncthreads();
        if (tid < 128) {
            float4 a0 = s_red[tid], a1 = s_red[128 + tid];
            float2 r;
            r.x = (a0.x + a1.x) * (0.5f / 128.0f) + (a0.z + a1.z) * (0.25f / 128.0f);
            r.y = (a0.y + a1.y) * (0.5f / 128.0f) + (a0.w + a1.w) * (0.25f / 128.0f);
            ((float2*)g_pooled)[(128 + b) * 128 + tid] = r;
        }
    } else {
        const int b = blk - 256;
        float2* sx = (float2*)smf;
        float2* sy = sx + 512;
        float2* sz = sy + 512;
        float* s_min = (float*)(sz + 512);
        float* s_sum4 = s_min + 1024;
        float* s_min4 = s_sum4 + 4;

        const float* pp = ppos + b * PPN * 3;
        for (int i = tid; i < PPN; i += 256) {
            ((float*)sx)[i] = pp[3 * i + 0];
            ((float*)sy)[i] = pp[3 * i + 1];
            ((float*)sz)[i] = pp[3 * i + 2];
        }
        __syncthreads();

        const int c = tid >> 5, lq = tid & 31;
        const float* lp = lpos + (b * LGN + lq * 4) * 3;
        uint64_t nlx[4], nly[4], nlz[4];
        #pragma unroll
        for (int q = 0; q < 4; q++) {
            float ax = -lp[3 * q + 0], ay = -lp[3 * q + 1], az = -lp[3 * q + 2];
            nlx[q] = pk2(ax, ax); nly[q] = pk2(ay, ay); nlz[q] = pk2(az, az);
        }
        float mlo[4] = {3.4e38f, 3.4e38f, 3.4e38f, 3.4e38f};
        float mhi[4] = {3.4e38f, 3.4e38f, 3.4e38f, 3.4e38f};
        const int p0 = c * 64;
        #pragma unroll 4
        for (int p = p0; p < p0 + 64; p++) {
            uint64_t px = pkf2(sx[p]), py = pkf2(sy[p]), pz = pkf2(sz[p]);
            #pragma unroll
            for (int q = 0; q < 4; q++) {
                uint64_t dx = f2add(px, nlx[q]);
                uint64_t dy = f2add(py, nly[q]);
                uint64_t dz = f2add(pz, nlz[q]);
                uint64_t d2 = f2mul(dx, dx);
                d2 = f2fma(dy, dy, d2);
                d2 = f2fma(dz, dz, d2);
                float2 v = upk(d2);
                mlo[q] = fminf(mlo[q], v.x);
                mhi[q] = fminf(mhi[q], v.y);
            }
        }
        #pragma unroll
        for (int q = 0; q < 4; q++) s_min[c * 128 + lq * 4 + q] = fminf(mlo[q], mhi[q]);
        __syncthreads();

        if (tid < 128) {
            float d2m = s_min[tid];
            #pragma unroll
            for (int cc = 1; cc < 8; cc++) d2m = fminf(d2m, s_min[cc * 128 + tid]);
            float d = sqrtf(d2m);
            float sumv = d, minv = d;
            #pragma unroll
            for (int off = 16; off > 0; off >>= 1) {
                sumv += __shfl_xor_sync(0xffffffffu, sumv, off);
                minv = fminf(minv, __shfl_xor_sync(0xffffffffu, minv, off));
            }
            if ((tid & 31) == 0) { s_sum4[tid >> 5] = sumv; s_min4[tid >> 5] = minv; }
        }
        __syncthreads();
        if (tid == 0) {
            float s = s_sum4[0] + s_sum4[1] + s_sum4[2] + s_sum4[3];
            float mn = fminf(fminf(s_min4[0], s_min4[1]), fminf(s_min4[2], s_min4[3]));
            g_contact[b * 2 + 0] = s * (1.0f / 128.0f);
            g_contact[b * 2 + 1] = mn;
        }
    }
}

// =====================================================================
// K_final: grid 64 x 512. 2 batches/block, split-K halves.
// =====================================================================
__global__ __launch_bounds__(512) void k_final(
    const float* __restrict__ Wa2, const float* __restrict__ ba2,
    float* __restrict__ out)
{
    __shared__ float2 s_pk[516];
    __shared__ float2 s_part[256];
    __shared__ float2 s_warp[8];
    const int tid = threadIdx.x;
    const int b0 = blockIdx.x * 2;

    for (int k = tid; k < 514; k += 512) {
        float v0, v1;
        if (k < 256)      { v0 = g_pooled[b0 * HD + k];              v1 = g_pooled[(b0 + 1) * HD + k]; }
        else if (k < 512) { v0 = g_pooled[(128 + b0) * HD + k - 256]; v1 = g_pooled[(129 + b0) * HD + k - 256]; }
        else              { v0 = g_contact[b0 * 2 + (k - 512)];       v1 = g_contact[(b0 + 1) * 2 + (k - 512)]; }
        s_pk[k] = make_float2(v0, v1);
    }
    if (tid == 0) s_pk[514] = make_float2(1.0f, 1.0f);
    __syncthreads();

    const int j = tid & 255, kh = tid >> 8;
    uint64_t acc = 0ull;
    if (kh == 0) {
        #pragma unroll 16
        for (int k = 0; k < 258; k++) {
            float w = g_M[k * HD + j];
            acc = f2fma(pkf2(s_pk[k]), pk2(w, w), acc);
        }
        s_part[j] = upk(acc);
    } else {
        #pragma unroll 16
        for (int k = 258; k < 515; k++) {
            float w = g_M[k * HD + j];
            acc = f2fma(pkf2(s_pk[k]), pk2(w, w), acc);
        }
    }
    __syncthreads();

    if (kh == 1) {
        float2 p = s_part[j], m = upk(acc);
        float x0 = p.x + m.x, x1 = p.y + m.y;
        float w2 = Wa2[j];
        float y0 = x0 * w2 / (1.0f + __expf(-x0));
        float y1 = x1 * w2 / (1.0f + __expf(-x1));
        #pragma unroll
        for (int off = 16; off > 0; off >>= 1) {
            y0 += __shfl_xor_sync(0xffffffffu, y0, off);
            y1 += __shfl_xor_sync(0xffffffffu, y1, off);
        }
        if ((tid & 31) == 0) s_warp[(tid >> 5) - 8] = make_float2(y0, y1);
    }
    __syncthreads();
    if (tid == 0) {
        float s0 = 0.0f, s1 = 0.0f;
        #pragma unroll
        for (int w = 0; w < 8; w++) { s0 += s_warp[w].x; s1 += s_warp[w].y; }
        out[b0 + 0] = s0 + ba2[0];
        out[b0 + 1] = s1 + ba2[0];
    }
}

extern "C" void kernel_launch(void* const* d_in, const int* in_sizes, int n_in,
                              void* d_out, int out_size) {
    const float* protein_pos = (const float*)d_in[0];
    const float* ligand_pos  = (const float*)d_in[1];
    const int*   p_elem      = (const int*)d_in[2];
    const int*   p_aa        = (const int*)d_in[3];
    const int*   p_bb        = (const int*)d_in[4];
    const int*   l_type      = (const int*)d_in[5];
    const float* E_elem = (const float*)d_in[8];
    const float* E_aa   = (const float*)d_in[9];
    const float* E_bb   = (const float*)d_in[10];
    const float* E_lig  = (const float*)d_in[11];
    const float* Wd1    = (const float*)d_in[12];
    const float* bd1    = (const float*)d_in[13];
    const float* Wd2    = (const float*)d_in[14];
    const float* bd2    = (const float*)d_in[15];
    const float* Wa1    = (const float*)d_in[16];
    const float* ba1    = (const float*)d_in[17];
    const float* Wa2    = (const float*)d_in[18];
    const float* ba2    = (const float*)d_in[19];
    float* out = (float*)d_out;

    const int bc_smem = 16384 * 4 + 8192 * 4 + 1024 * 8 + 256 * 16;
    cudaFuncSetAttribute(k_bc, cudaFuncAttributeMaxDynamicSharedMemorySize, bc_smem);

    k_pre<<<91, 256>>>(E_elem, E_aa, E_bb, E_lig, Wd1, bd1, Wd2, bd2, Wa1, ba1);
    k_bc<<<384, 256, bc_smem>>>(protein_pos, ligand_pos, p_elem, p_aa, p_bb, l_type);
    k_final<<<64, 512>>>(Wa2, ba2, out);
}